// round 6
// baseline (speedup 1.0000x reference)
#include <cuda_runtime.h>
#include <math.h>

#define BB 16
#define SS 1024
#define NIN 7
#define NHID 28
#define HEADS 7
#define HD 4

// Scratch (device globals — no allocation allowed)
__device__ float g_Q [BB*HEADS*SS*HD];
__device__ float g_K [BB*HEADS*SS*HD];
__device__ float g_V [BB*HEADS*SS*HD];
__device__ float g_AO[BB*SS*NHID];
__device__ float g_Q2[BB*SS*NHID];
__device__ float g_K2[BB*SS*NHID];

// ---------------------------------------------------------------------------
// helpers
// ---------------------------------------------------------------------------
typedef unsigned long long u64;
__device__ __forceinline__ float ex2(float x) {            // single MUFU.EX2
    float r; asm("ex2.approx.ftz.f32 %0, %1;" : "=f"(r) : "f"(x)); return r;
}
__device__ __forceinline__ u64 pk2(float a, float b) {
    u64 r; asm("mov.b64 %0, {%1,%2};" : "=l"(r) : "f"(a), "f"(b)); return r;
}
__device__ __forceinline__ void up2(u64 v, float& a, float& b) {
    asm("mov.b64 {%0,%1}, %2;" : "=f"(a), "=f"(b) : "l"(v));
}
__device__ __forceinline__ u64 f2fma(u64 a, u64 b, u64 c) {
    u64 d; asm("fma.rn.f32x2 %0, %1, %2, %3;" : "=l"(d) : "l"(a), "l"(b), "l"(c)); return d;
}
__device__ __forceinline__ u64 f2mul(u64 a, u64 b) {
    u64 d; asm("mul.rn.f32x2 %0, %1, %2;" : "=l"(d) : "l"(a), "l"(b)); return d;
}
__device__ __forceinline__ u64 f2add(u64 a, u64 b) {
    u64 d; asm("add.rn.f32x2 %0, %1, %2;" : "=l"(d) : "l"(a), "l"(b)); return d;
}

// ---------------------------------------------------------------------------
// K1: QKV projection. 1 thread per (b,s) row. Q/K/V stored [B,H,S,4] (float4).
// ---------------------------------------------------------------------------
__global__ void k_qkv(const float* __restrict__ x,
                      const float* __restrict__ Wq, const float* __restrict__ bq,
                      const float* __restrict__ Wk, const float* __restrict__ bk,
                      const float* __restrict__ Wv, const float* __restrict__ bv) {
    __shared__ float sw[672];
    int tid = threadIdx.x;
    for (int i = tid; i < 196; i += blockDim.x) {
        sw[i] = Wq[i]; sw[224 + i] = Wk[i]; sw[448 + i] = Wv[i];
    }
    if (tid < 28) { sw[196 + tid] = bq[tid]; sw[420 + tid] = bk[tid]; sw[644 + tid] = bv[tid]; }
    __syncthreads();

    int r = blockIdx.x * blockDim.x + tid;        // 0..16383
    int b = r >> 10, s = r & 1023;

    float xv[7];
#pragma unroll
    for (int i = 0; i < 7; i++) xv[i] = x[r * 7 + i];

#pragma unroll
    for (int h = 0; h < 7; h++) {
        float qa[4], ka[4], va[4];
#pragma unroll
        for (int d = 0; d < 4; d++) {
            int j = h * 4 + d;
            float aq = sw[196 + j], ak = sw[420 + j], av = sw[644 + j];
#pragma unroll
            for (int i = 0; i < 7; i++) {
                float xi = xv[i];
                aq += xi * sw[i * 28 + j];
                ak += xi * sw[224 + i * 28 + j];
                av += xi * sw[448 + i * 28 + j];
            }
            qa[d] = aq; ka[d] = ak; va[d] = av;
        }
        int o = (b * 7 + h) * 1024 + s;
        reinterpret_cast<float4*>(g_Q)[o] = make_float4(qa[0], qa[1], qa[2], qa[3]);
        reinterpret_cast<float4*>(g_K)[o] = make_float4(ka[0], ka[1], ka[2], ka[3]);
        reinterpret_cast<float4*>(g_V)[o] = make_float4(va[0], va[1], va[2], va[3]);
    }
}

// ---------------------------------------------------------------------------
// K2: first attention. 2 q rows per thread packed f32x2; K/V duplicated (k,k)
// in smem so each broadcast LDS serves both rows. Max-free softmax, ex2.approx.
// 128 thr, grid (4,7,16)=448 -> 3.03 waves; smem 64KB -> 3 CTA/SM = 12 warps.
// ---------------------------------------------------------------------------
__global__ void __launch_bounds__(128) k_attn1() {
    extern __shared__ ulonglong2 s1[];           // [0,2048): Kdup, [2048,4096): Vdup
    ulonglong2* Ks = s1;
    ulonglong2* Vs = s1 + 2048;
    int b = blockIdx.z, h = blockIdx.y, chunk = blockIdx.x;   // chunk in [0,4)
    int bh = b * 7 + h;
    const float4* Kg = reinterpret_cast<const float4*>(g_K) + bh * 1024;
    const float4* Vg = reinterpret_cast<const float4*>(g_V) + bh * 1024;
    for (int t = threadIdx.x; t < 1024; t += 128) {
        float4 kk = Kg[t];
        Ks[2*t]   = make_ulonglong2(pk2(kk.x, kk.x), pk2(kk.y, kk.y));
        Ks[2*t+1] = make_ulonglong2(pk2(kk.z, kk.z), pk2(kk.w, kk.w));
        float4 vv = Vg[t];
        Vs[2*t]   = make_ulonglong2(pk2(vv.x, vv.x), pk2(vv.y, vv.y));
        Vs[2*t+1] = make_ulonglong2(pk2(vv.z, vv.z), pk2(vv.w, vv.w));
    }
    __syncthreads();

    int qA = chunk * 256 + threadIdx.x;          // rows qA, qA+128
    float4 qa = reinterpret_cast<const float4*>(g_Q)[bh * 1024 + qA];
    float4 qb = reinterpret_cast<const float4*>(g_Q)[bh * 1024 + qA + 128];
    const float c = 0.5f * 1.4426950408889634f;  // 1/sqrt(4) * log2(e)
    u64 qp0 = pk2(qa.x * c, qb.x * c);
    u64 qp1 = pk2(qa.y * c, qb.y * c);
    u64 qp2 = pk2(qa.z * c, qb.z * c);
    u64 qp3 = pk2(qa.w * c, qb.w * c);

    u64 acc0 = 0ull, acc1 = 0ull, acc2 = 0ull, acc3 = 0ull, l2 = 0ull;
#pragma unroll 4
    for (int k = 0; k < 1024; k++) {
        ulonglong2 k01 = Ks[2*k];
        ulonglong2 k23 = Ks[2*k+1];
        u64 s2 = f2mul(qp0, k01.x);
        s2 = f2fma(qp1, k01.y, s2);
        s2 = f2fma(qp2, k23.x, s2);
        s2 = f2fma(qp3, k23.y, s2);
        float sa, sb; up2(s2, sa, sb);
        u64 p2 = pk2(ex2(sa), ex2(sb));
        ulonglong2 v01 = Vs[2*k];
        ulonglong2 v23 = Vs[2*k+1];
        acc0 = f2fma(p2, v01.x, acc0);
        acc1 = f2fma(p2, v01.y, acc1);
        acc2 = f2fma(p2, v23.x, acc2);
        acc3 = f2fma(p2, v23.y, acc3);
        l2 = f2add(l2, p2);
    }
    float lA, lB; up2(l2, lA, lB);
    float iA = 1.f / lA, iB = 1.f / lB;
    float x0, y0, x1, y1, x2, y2, x3, y3;
    up2(acc0, x0, y0); up2(acc1, x1, y1); up2(acc2, x2, y2); up2(acc3, x3, y3);
    *reinterpret_cast<float4*>(g_AO + ((b * 1024 + qA) * 28 + h * 4)) =
        make_float4(x0 * iA, x1 * iA, x2 * iA, x3 * iA);
    *reinterpret_cast<float4*>(g_AO + ((b * 1024 + qA + 128) * 28 + h * 4)) =
        make_float4(y0 * iB, y1 * iB, y2 * iB, y3 * iB);
}

// ---------------------------------------------------------------------------
// K3: LayerNorm(28) + FFN(28->7) + ReLU + residual -> out7 (d_out head),
// then Q2/K2 projections (7->28) into scratch. 1 thread per row.
// ---------------------------------------------------------------------------
__global__ void k_lnffn(const float* __restrict__ x,
                        const float* __restrict__ lnw, const float* __restrict__ lnb,
                        const float* __restrict__ W1,  const float* __restrict__ b1,
                        const float* __restrict__ Wq2, const float* __restrict__ bq2,
                        const float* __restrict__ Wk2, const float* __restrict__ bk2,
                        float* __restrict__ out7) {
    __shared__ float s_lnw[28], s_lnb[28], s_W1[196], s_b1[7];
    __shared__ float s_Wq2[196], s_bq2[28], s_Wk2[196], s_bk2[28];
    int tid = threadIdx.x;
    for (int i = tid; i < 196; i += blockDim.x) { s_W1[i] = W1[i]; s_Wq2[i] = Wq2[i]; s_Wk2[i] = Wk2[i]; }
    if (tid < 28) { s_lnw[tid] = lnw[tid]; s_lnb[tid] = lnb[tid]; s_bq2[tid] = bq2[tid]; s_bk2[tid] = bk2[tid]; }
    if (tid < 7)  { s_b1[tid] = b1[tid]; }
    __syncthreads();

    int r = blockIdx.x * blockDim.x + tid;
    float a[28];
    const float4* ap = reinterpret_cast<const float4*>(g_AO + r * 28);
#pragma unroll
    for (int i = 0; i < 7; i++) {
        float4 t = ap[i];
        a[4*i] = t.x; a[4*i+1] = t.y; a[4*i+2] = t.z; a[4*i+3] = t.w;
    }
    float mu = 0.f;
#pragma unroll
    for (int j = 0; j < 28; j++) mu += a[j];
    mu *= (1.f / 28.f);
    float var = 0.f;
#pragma unroll
    for (int j = 0; j < 28; j++) { float d = a[j] - mu; var += d * d; }
    var *= (1.f / 28.f);
    float rs = rsqrtf(var + 1e-5f);

    float y[28];
#pragma unroll
    for (int j = 0; j < 28; j++) y[j] = (a[j] - mu) * rs * s_lnw[j] + s_lnb[j];

    float z[7];
#pragma unroll
    for (int i = 0; i < 7; i++) {
        float t = s_b1[i];
#pragma unroll
        for (int j = 0; j < 28; j++) t += y[j] * s_W1[j * 7 + i];
        t = fmaxf(t, 0.f) + x[r * 7 + i];
        z[i] = t;
        out7[r * 7 + i] = t;
    }
#pragma unroll
    for (int j = 0; j < 28; j++) {
        float tq = s_bq2[j], tk = s_bk2[j];
#pragma unroll
        for (int i = 0; i < 7; i++) {
            tq += z[i] * s_Wq2[i * 28 + j];
            tk += z[i] * s_Wk2[i * 28 + j];
        }
        g_Q2[r * 28 + j] = tq;
        g_K2[r * 28 + j] = tk;
    }
}

// ---------------------------------------------------------------------------
// K4: second attention weights. K2[b] (112KB) in dynamic SMEM.
// Block = 512 threads (16 warps/SM, 4/SMSP) -> latency actually hidden.
// 2 q rows per warp (Qp = 28 u64 regs -> ~105 regs, fits 512thr in 64K RF).
// Max-free softmax streams p to gmem + L2-hit readback normalize.
// Tiles of 32 rows -> grid (32,16) = 512 blocks = 3.46 waves.
// ---------------------------------------------------------------------------
__global__ void __launch_bounds__(512, 1) k_attn2(float* __restrict__ out) {
    extern __shared__ float K2s[];                 // 1024*28 floats
    int b = blockIdx.y, tile = blockIdx.x;         // 32 tiles of 32 q rows
    {
        const float4* src = reinterpret_cast<const float4*>(g_K2 + b * SS * 28);
        float4* dst = reinterpret_cast<float4*>(K2s);
        for (int t = threadIdx.x; t < 1024 * 7; t += 512) dst[t] = src[t];
    }
    __syncthreads();

    int warp = threadIdx.x >> 5, lane = threadIdx.x & 31;
    const float SC2 = 1.4426950408889634f / 2.6457513110645906f; // log2(e)/sqrt(7)

    int q0 = tile * 32 + warp * 2;                 // rows q0, q0+1

    u64 Qp[2][14];
#pragma unroll
    for (int r = 0; r < 2; r++) {
        const float4* qp = reinterpret_cast<const float4*>(g_Q2 + (b * 1024 + q0 + r) * 28);
#pragma unroll
        for (int i = 0; i < 7; i++) {
            float4 t = qp[i];
            Qp[r][2*i]   = pk2(t.x * SC2, t.y * SC2);
            Qp[r][2*i+1] = pk2(t.z * SC2, t.w * SC2);
        }
    }

    float* o0 = out + (b * 1024 + q0) * 1024;
    float su0 = 0.f, su1 = 0.f;
#pragma unroll 2
    for (int i = 0; i < 32; i++) {
        int k = i * 32 + lane;
        const ulonglong2* kr = reinterpret_cast<const ulonglong2*>(&K2s[k * 28]);
        ulonglong2 kk[7];
#pragma unroll
        for (int j = 0; j < 7; j++) kk[j] = kr[j];
        float p[2];
#pragma unroll
        for (int r = 0; r < 2; r++) {
            u64 acc = f2mul(Qp[r][0], kk[0].x);
            acc = f2fma(Qp[r][1],  kk[0].y, acc);
            acc = f2fma(Qp[r][2],  kk[1].x, acc);
            acc = f2fma(Qp[r][3],  kk[1].y, acc);
            acc = f2fma(Qp[r][4],  kk[2].x, acc);
            acc = f2fma(Qp[r][5],  kk[2].y, acc);
            acc = f2fma(Qp[r][6],  kk[3].x, acc);
            acc = f2fma(Qp[r][7],  kk[3].y, acc);
            acc = f2fma(Qp[r][8],  kk[4].x, acc);
            acc = f2fma(Qp[r][9],  kk[4].y, acc);
            acc = f2fma(Qp[r][10], kk[5].x, acc);
            acc = f2fma(Qp[r][11], kk[5].y, acc);
            acc = f2fma(Qp[r][12], kk[6].x, acc);
            acc = f2fma(Qp[r][13], kk[6].y, acc);
            float lo, hi; up2(acc, lo, hi);
            p[r] = ex2(lo + hi);
        }
        su0 += p[0]; su1 += p[1];
        o0[k]        = p[0];
        o0[1024 + k] = p[1];
    }
#pragma unroll
    for (int o = 16; o > 0; o >>= 1) {
        su0 += __shfl_xor_sync(0xffffffffu, su0, o);
        su1 += __shfl_xor_sync(0xffffffffu, su1, o);
    }
    float iv0 = 1.f / su0, iv1 = 1.f / su1;

    // readback (L2-resident) + normalize
#pragma unroll 4
    for (int i = 0; i < 32; i++) {
        int k = i * 32 + lane;
        o0[k]        *= iv0;
        o0[1024 + k] *= iv1;
    }
}

// ---------------------------------------------------------------------------
extern "C" void kernel_launch(void* const* d_in, const int* in_sizes, int n_in,
                              void* d_out, int out_size) {
    const float* x    = (const float*)d_in[0];
    const float* Wq   = (const float*)d_in[1];
    const float* bq   = (const float*)d_in[2];
    const float* Wk   = (const float*)d_in[3];
    const float* bk   = (const float*)d_in[4];
    const float* Wv   = (const float*)d_in[5];
    const float* bv   = (const float*)d_in[6];
    const float* lnw  = (const float*)d_in[7];
    const float* lnb  = (const float*)d_in[8];
    const float* W1   = (const float*)d_in[9];
    const float* b1   = (const float*)d_in[10];
    const float* Wq2  = (const float*)d_in[11];
    const float* bq2  = (const float*)d_in[12];
    const float* Wk2  = (const float*)d_in[13];
    const float* bk2  = (const float*)d_in[14];
    float* out = (float*)d_out;

    cudaFuncSetAttribute(k_attn1, cudaFuncAttributeMaxDynamicSharedMemorySize, 65536);
    cudaFuncSetAttribute(k_attn2, cudaFuncAttributeMaxDynamicSharedMemorySize,
                         1024 * 28 * sizeof(float));

    k_qkv<<<128, 128>>>(x, Wq, bq, Wk, bk, Wv, bv);
    k_attn1<<<dim3(4, 7, 16), 128, 65536>>>();
    k_lnffn<<<128, 128>>>(x, lnw, lnb, W1, b1, Wq2, bq2, Wk2, bk2, out);
    k_attn2<<<dim3(32, 16), 512, 1024 * 28 * sizeof(float)>>>(out + BB * SS * NIN);
}

// round 7
// speedup vs baseline: 1.0848x; 1.0848x over previous
#include <cuda_runtime.h>
#include <math.h>

#define BB 16
#define SS 1024
#define NIN 7
#define NHID 28
#define HEADS 7
#define HD 4

// Scratch (device globals — no allocation allowed)
__device__ float g_Q [BB*HEADS*SS*HD];
__device__ float g_K [BB*HEADS*SS*HD];
__device__ float g_V [BB*HEADS*SS*HD];
__device__ float g_AO[BB*SS*NHID];
__device__ float g_Q2[BB*SS*NHID];
__device__ float g_K2[BB*SS*NHID];

// ---------------------------------------------------------------------------
// helpers
// ---------------------------------------------------------------------------
typedef unsigned long long u64;
__device__ __forceinline__ float ex2(float x) {            // single MUFU.EX2
    float r; asm("ex2.approx.ftz.f32 %0, %1;" : "=f"(r) : "f"(x)); return r;
}
__device__ __forceinline__ u64 pk2(float a, float b) {
    u64 r; asm("mov.b64 %0, {%1,%2};" : "=l"(r) : "f"(a), "f"(b)); return r;
}
__device__ __forceinline__ void up2(u64 v, float& a, float& b) {
    asm("mov.b64 {%0,%1}, %2;" : "=f"(a), "=f"(b) : "l"(v));
}
__device__ __forceinline__ u64 f2fma(u64 a, u64 b, u64 c) {
    u64 d; asm("fma.rn.f32x2 %0, %1, %2, %3;" : "=l"(d) : "l"(a), "l"(b), "l"(c)); return d;
}
__device__ __forceinline__ u64 f2mul(u64 a, u64 b) {
    u64 d; asm("mul.rn.f32x2 %0, %1, %2;" : "=l"(d) : "l"(a), "l"(b)); return d;
}
__device__ __forceinline__ u64 f2add(u64 a, u64 b) {
    u64 d; asm("add.rn.f32x2 %0, %1, %2;" : "=l"(d) : "l"(a), "l"(b)); return d;
}

// ---------------------------------------------------------------------------
// K1: QKV projection. 1 thread per (b,s) row. Q/K/V stored [B,H,S,4] (float4).
// ---------------------------------------------------------------------------
__global__ void k_qkv(const float* __restrict__ x,
                      const float* __restrict__ Wq, const float* __restrict__ bq,
                      const float* __restrict__ Wk, const float* __restrict__ bk,
                      const float* __restrict__ Wv, const float* __restrict__ bv) {
    __shared__ float sw[672];
    int tid = threadIdx.x;
    for (int i = tid; i < 196; i += blockDim.x) {
        sw[i] = Wq[i]; sw[224 + i] = Wk[i]; sw[448 + i] = Wv[i];
    }
    if (tid < 28) { sw[196 + tid] = bq[tid]; sw[420 + tid] = bk[tid]; sw[644 + tid] = bv[tid]; }
    __syncthreads();

    int r = blockIdx.x * blockDim.x + tid;        // 0..16383
    int b = r >> 10, s = r & 1023;

    float xv[7];
#pragma unroll
    for (int i = 0; i < 7; i++) xv[i] = x[r * 7 + i];

#pragma unroll
    for (int h = 0; h < 7; h++) {
        float qa[4], ka[4], va[4];
#pragma unroll
        for (int d = 0; d < 4; d++) {
            int j = h * 4 + d;
            float aq = sw[196 + j], ak = sw[420 + j], av = sw[644 + j];
#pragma unroll
            for (int i = 0; i < 7; i++) {
                float xi = xv[i];
                aq += xi * sw[i * 28 + j];
                ak += xi * sw[224 + i * 28 + j];
                av += xi * sw[448 + i * 28 + j];
            }
            qa[d] = aq; ka[d] = ak; va[d] = av;
        }
        int o = (b * 7 + h) * 1024 + s;
        reinterpret_cast<float4*>(g_Q)[o] = make_float4(qa[0], qa[1], qa[2], qa[3]);
        reinterpret_cast<float4*>(g_K)[o] = make_float4(ka[0], ka[1], ka[2], ka[3]);
        reinterpret_cast<float4*>(g_V)[o] = make_float4(va[0], va[1], va[2], va[3]);
    }
}

// ---------------------------------------------------------------------------
// K2: first attention. 2 q rows per thread packed f32x2; K/V duplicated (k,k)
// in smem so each broadcast LDS serves both rows. Max-free softmax, ex2.approx.
// 128 thr, grid (4,7,16)=448 -> 3.03 waves; smem 64KB -> 3 CTA/SM = 12 warps.
// ---------------------------------------------------------------------------
__global__ void __launch_bounds__(128) k_attn1() {
    extern __shared__ ulonglong2 s1[];           // [0,2048): Kdup, [2048,4096): Vdup
    ulonglong2* Ks = s1;
    ulonglong2* Vs = s1 + 2048;
    int b = blockIdx.z, h = blockIdx.y, chunk = blockIdx.x;   // chunk in [0,4)
    int bh = b * 7 + h;
    const float4* Kg = reinterpret_cast<const float4*>(g_K) + bh * 1024;
    const float4* Vg = reinterpret_cast<const float4*>(g_V) + bh * 1024;
    for (int t = threadIdx.x; t < 1024; t += 128) {
        float4 kk = Kg[t];
        Ks[2*t]   = make_ulonglong2(pk2(kk.x, kk.x), pk2(kk.y, kk.y));
        Ks[2*t+1] = make_ulonglong2(pk2(kk.z, kk.z), pk2(kk.w, kk.w));
        float4 vv = Vg[t];
        Vs[2*t]   = make_ulonglong2(pk2(vv.x, vv.x), pk2(vv.y, vv.y));
        Vs[2*t+1] = make_ulonglong2(pk2(vv.z, vv.z), pk2(vv.w, vv.w));
    }
    __syncthreads();

    int qA = chunk * 256 + threadIdx.x;          // rows qA, qA+128
    float4 qa = reinterpret_cast<const float4*>(g_Q)[bh * 1024 + qA];
    float4 qb = reinterpret_cast<const float4*>(g_Q)[bh * 1024 + qA + 128];
    const float c = 0.5f * 1.4426950408889634f;  // 1/sqrt(4) * log2(e)
    u64 qp0 = pk2(qa.x * c, qb.x * c);
    u64 qp1 = pk2(qa.y * c, qb.y * c);
    u64 qp2 = pk2(qa.z * c, qb.z * c);
    u64 qp3 = pk2(qa.w * c, qb.w * c);

    u64 acc0 = 0ull, acc1 = 0ull, acc2 = 0ull, acc3 = 0ull, l2 = 0ull;
#pragma unroll 4
    for (int k = 0; k < 1024; k++) {
        ulonglong2 k01 = Ks[2*k];
        ulonglong2 k23 = Ks[2*k+1];
        u64 s2 = f2mul(qp0, k01.x);
        s2 = f2fma(qp1, k01.y, s2);
        s2 = f2fma(qp2, k23.x, s2);
        s2 = f2fma(qp3, k23.y, s2);
        float sa, sb; up2(s2, sa, sb);
        u64 p2 = pk2(ex2(sa), ex2(sb));
        ulonglong2 v01 = Vs[2*k];
        ulonglong2 v23 = Vs[2*k+1];
        acc0 = f2fma(p2, v01.x, acc0);
        acc1 = f2fma(p2, v01.y, acc1);
        acc2 = f2fma(p2, v23.x, acc2);
        acc3 = f2fma(p2, v23.y, acc3);
        l2 = f2add(l2, p2);
    }
    float lA, lB; up2(l2, lA, lB);
    float iA = 1.f / lA, iB = 1.f / lB;
    float x0, y0, x1, y1, x2, y2, x3, y3;
    up2(acc0, x0, y0); up2(acc1, x1, y1); up2(acc2, x2, y2); up2(acc3, x3, y3);
    *reinterpret_cast<float4*>(g_AO + ((b * 1024 + qA) * 28 + h * 4)) =
        make_float4(x0 * iA, x1 * iA, x2 * iA, x3 * iA);
    *reinterpret_cast<float4*>(g_AO + ((b * 1024 + qA + 128) * 28 + h * 4)) =
        make_float4(y0 * iB, y1 * iB, y2 * iB, y3 * iB);
}

// ---------------------------------------------------------------------------
// K3: LayerNorm(28) + FFN(28->7) + ReLU + residual -> out7 (d_out head),
// then Q2/K2 projections (7->28) into scratch. 1 thread per row.
// ---------------------------------------------------------------------------
__global__ void k_lnffn(const float* __restrict__ x,
                        const float* __restrict__ lnw, const float* __restrict__ lnb,
                        const float* __restrict__ W1,  const float* __restrict__ b1,
                        const float* __restrict__ Wq2, const float* __restrict__ bq2,
                        const float* __restrict__ Wk2, const float* __restrict__ bk2,
                        float* __restrict__ out7) {
    __shared__ float s_lnw[28], s_lnb[28], s_W1[196], s_b1[7];
    __shared__ float s_Wq2[196], s_bq2[28], s_Wk2[196], s_bk2[28];
    int tid = threadIdx.x;
    for (int i = tid; i < 196; i += blockDim.x) { s_W1[i] = W1[i]; s_Wq2[i] = Wq2[i]; s_Wk2[i] = Wk2[i]; }
    if (tid < 28) { s_lnw[tid] = lnw[tid]; s_lnb[tid] = lnb[tid]; s_bq2[tid] = bq2[tid]; s_bk2[tid] = bk2[tid]; }
    if (tid < 7)  { s_b1[tid] = b1[tid]; }
    __syncthreads();

    int r = blockIdx.x * blockDim.x + tid;
    float a[28];
    const float4* ap = reinterpret_cast<const float4*>(g_AO + r * 28);
#pragma unroll
    for (int i = 0; i < 7; i++) {
        float4 t = ap[i];
        a[4*i] = t.x; a[4*i+1] = t.y; a[4*i+2] = t.z; a[4*i+3] = t.w;
    }
    float mu = 0.f;
#pragma unroll
    for (int j = 0; j < 28; j++) mu += a[j];
    mu *= (1.f / 28.f);
    float var = 0.f;
#pragma unroll
    for (int j = 0; j < 28; j++) { float d = a[j] - mu; var += d * d; }
    var *= (1.f / 28.f);
    float rs = rsqrtf(var + 1e-5f);

    float y[28];
#pragma unroll
    for (int j = 0; j < 28; j++) y[j] = (a[j] - mu) * rs * s_lnw[j] + s_lnb[j];

    float z[7];
#pragma unroll
    for (int i = 0; i < 7; i++) {
        float t = s_b1[i];
#pragma unroll
        for (int j = 0; j < 28; j++) t += y[j] * s_W1[j * 7 + i];
        t = fmaxf(t, 0.f) + x[r * 7 + i];
        z[i] = t;
        out7[r * 7 + i] = t;
    }
#pragma unroll
    for (int j = 0; j < 28; j++) {
        float tq = s_bq2[j], tk = s_bk2[j];
#pragma unroll
        for (int i = 0; i < 7; i++) {
            tq += z[i] * s_Wq2[i * 28 + j];
            tk += z[i] * s_Wk2[i * 28 + j];
        }
        g_Q2[r * 28 + j] = tq;
        g_K2[r * 28 + j] = tk;
    }
}

// ---------------------------------------------------------------------------
// K4: second attention weights — K2 IN REGISTERS, Q2 broadcast from smem.
// Block = 512 thr (16 warps). Warp w owns k rows {w*64+lane, w*64+32+lane}
// (2x14 u64 regs, loaded once via LDG). Loop over 32 q rows: 7 broadcast
// LDS.128 (1 crossbar phase each), 28 f2fma in two independent chains,
// ex2, coalesced STG of p, 5-shfl k-sum -> smem partials. Tail: per-q
// 1/sum, then L2-hit readback normalize. smem ~6KB, regs ~90.
// ---------------------------------------------------------------------------
__global__ void __launch_bounds__(512, 1) k_attn2(float* __restrict__ out) {
    __shared__ float sQ[32 * 28];          // q tile, rows 112B apart (16B aligned)
    __shared__ float sPart[32][17];        // per-(q, warp) partial sums (pad 17)
    __shared__ float sInv[32];

    int b = blockIdx.y, tile = blockIdx.x;             // 32 tiles of 32 q rows
    int warp = threadIdx.x >> 5, lane = threadIdx.x & 31;
    const float SC2 = 1.4426950408889634f / 2.6457513110645906f; // log2(e)/sqrt(7)

    // Load + scale Q2 tile into smem
    for (int t = threadIdx.x; t < 32 * 28; t += 512)
        sQ[t] = g_Q2[(b * 1024 + tile * 32) * 28 + t] * SC2;

    // Load this warp's two K2 rows into registers (once per block)
    int k0 = warp * 64 + lane;
    int k1 = k0 + 32;
    ulonglong2 kA[7], kB[7];
    {
        const ulonglong2* a = reinterpret_cast<const ulonglong2*>(g_K2 + (b * 1024 + k0) * 28);
        const ulonglong2* c = reinterpret_cast<const ulonglong2*>(g_K2 + (b * 1024 + k1) * 28);
#pragma unroll
        for (int j = 0; j < 7; j++) { kA[j] = a[j]; kB[j] = c[j]; }
    }
    __syncthreads();

    float* obase = out + (b * 1024 + tile * 32) * 1024;

#pragma unroll 2
    for (int q = 0; q < 32; q++) {
        const ulonglong2* qp = reinterpret_cast<const ulonglong2*>(sQ + q * 28);
        ulonglong2 qv[7];
#pragma unroll
        for (int j = 0; j < 7; j++) qv[j] = qp[j];      // broadcast LDS (N=1)

        u64 accA = f2mul(qv[0].x, kA[0].x);
        u64 accB = f2mul(qv[0].x, kB[0].x);
        accA = f2fma(qv[0].y, kA[0].y, accA);  accB = f2fma(qv[0].y, kB[0].y, accB);
        accA = f2fma(qv[1].x, kA[1].x, accA);  accB = f2fma(qv[1].x, kB[1].x, accB);
        accA = f2fma(qv[1].y, kA[1].y, accA);  accB = f2fma(qv[1].y, kB[1].y, accB);
        accA = f2fma(qv[2].x, kA[2].x, accA);  accB = f2fma(qv[2].x, kB[2].x, accB);
        accA = f2fma(qv[2].y, kA[2].y, accA);  accB = f2fma(qv[2].y, kB[2].y, accB);
        accA = f2fma(qv[3].x, kA[3].x, accA);  accB = f2fma(qv[3].x, kB[3].x, accB);
        accA = f2fma(qv[3].y, kA[3].y, accA);  accB = f2fma(qv[3].y, kB[3].y, accB);
        accA = f2fma(qv[4].x, kA[4].x, accA);  accB = f2fma(qv[4].x, kB[4].x, accB);
        accA = f2fma(qv[4].y, kA[4].y, accA);  accB = f2fma(qv[4].y, kB[4].y, accB);
        accA = f2fma(qv[5].x, kA[5].x, accA);  accB = f2fma(qv[5].x, kB[5].x, accB);
        accA = f2fma(qv[5].y, kA[5].y, accA);  accB = f2fma(qv[5].y, kB[5].y, accB);
        accA = f2fma(qv[6].x, kA[6].x, accA);  accB = f2fma(qv[6].x, kB[6].x, accB);
        accA = f2fma(qv[6].y, kA[6].y, accA);  accB = f2fma(qv[6].y, kB[6].y, accB);

        float aLo, aHi, bLo, bHi;
        up2(accA, aLo, aHi); up2(accB, bLo, bHi);
        float pA = ex2(aLo + aHi);
        float pB = ex2(bLo + bHi);

        float s = pA + pB;
#pragma unroll
        for (int o = 16; o > 0; o >>= 1)
            s += __shfl_xor_sync(0xffffffffu, s, o);
        if (lane == 0) sPart[q][warp] = s;

        obase[q * 1024 + k0] = pA;
        obase[q * 1024 + k1] = pB;
    }
    __syncthreads();

    if (threadIdx.x < 32) {
        float s = 0.f;
#pragma unroll
        for (int w = 0; w < 16; w++) s += sPart[threadIdx.x][w];
        sInv[threadIdx.x] = 1.f / s;
    }
    __syncthreads();

    // normalize readback (L2-resident): 32768 elems / 512 thr = 64 each
#pragma unroll 4
    for (int t = threadIdx.x; t < 32 * 1024; t += 512) {
        int q = t >> 10;
        obase[t] *= sInv[q];
    }
}

// ---------------------------------------------------------------------------
extern "C" void kernel_launch(void* const* d_in, const int* in_sizes, int n_in,
                              void* d_out, int out_size) {
    const float* x    = (const float*)d_in[0];
    const float* Wq   = (const float*)d_in[1];
    const float* bq   = (const float*)d_in[2];
    const float* Wk   = (const float*)d_in[3];
    const float* bk   = (const float*)d_in[4];
    const float* Wv   = (const float*)d_in[5];
    const float* bv   = (const float*)d_in[6];
    const float* lnw  = (const float*)d_in[7];
    const float* lnb  = (const float*)d_in[8];
    const float* W1   = (const float*)d_in[9];
    const float* b1   = (const float*)d_in[10];
    const float* Wq2  = (const float*)d_in[11];
    const float* bq2  = (const float*)d_in[12];
    const float* Wk2  = (const float*)d_in[13];
    const float* bk2  = (const float*)d_in[14];
    float* out = (float*)d_out;

    cudaFuncSetAttribute(k_attn1, cudaFuncAttributeMaxDynamicSharedMemorySize, 65536);

    k_qkv<<<128, 128>>>(x, Wq, bq, Wk, bk, Wv, bv);
    k_attn1<<<dim3(4, 7, 16), 128, 65536>>>();
    k_lnffn<<<128, 128>>>(x, lnw, lnb, W1, b1, Wq2, bq2, Wk2, bk2, out);
    k_attn2<<<dim3(32, 16), 512>>>(out + BB * SS * NIN);
}

// round 8
// speedup vs baseline: 1.1480x; 1.0582x over previous
#include <cuda_runtime.h>
#include <math.h>

#define BB 16
#define SS 1024
#define NIN 7
#define NHID 28
#define HEADS 7
#define HD 4

// Scratch (device globals — no allocation allowed)
__device__ float g_Q [BB*HEADS*SS*HD];
__device__ float g_K [BB*HEADS*SS*HD];
__device__ float g_V [BB*HEADS*SS*HD];
__device__ float g_AO[BB*SS*NHID];
__device__ float g_Q2[BB*SS*NHID];
__device__ float g_K2[BB*SS*NHID];

// ---------------------------------------------------------------------------
// helpers
// ---------------------------------------------------------------------------
typedef unsigned long long u64;
__device__ __forceinline__ float ex2(float x) {            // single MUFU.EX2
    float r; asm("ex2.approx.ftz.f32 %0, %1;" : "=f"(r) : "f"(x)); return r;
}
__device__ __forceinline__ u64 pk2(float a, float b) {
    u64 r; asm("mov.b64 %0, {%1,%2};" : "=l"(r) : "f"(a), "f"(b)); return r;
}
__device__ __forceinline__ void up2(u64 v, float& a, float& b) {
    asm("mov.b64 {%0,%1}, %2;" : "=f"(a), "=f"(b) : "l"(v));
}
__device__ __forceinline__ u64 f2fma(u64 a, u64 b, u64 c) {
    u64 d; asm("fma.rn.f32x2 %0, %1, %2, %3;" : "=l"(d) : "l"(a), "l"(b), "l"(c)); return d;
}
__device__ __forceinline__ u64 f2mul(u64 a, u64 b) {
    u64 d; asm("mul.rn.f32x2 %0, %1, %2;" : "=l"(d) : "l"(a), "l"(b)); return d;
}
__device__ __forceinline__ u64 f2add(u64 a, u64 b) {
    u64 d; asm("add.rn.f32x2 %0, %1, %2;" : "=l"(d) : "l"(a), "l"(b)); return d;
}

// ---------------------------------------------------------------------------
// K1: QKV projection. 1 thread per (b,s) row. Q/K/V stored [B,H,S,4] (float4).
// ---------------------------------------------------------------------------
__global__ void k_qkv(const float* __restrict__ x,
                      const float* __restrict__ Wq, const float* __restrict__ bq,
                      const float* __restrict__ Wk, const float* __restrict__ bk,
                      const float* __restrict__ Wv, const float* __restrict__ bv) {
    __shared__ float sw[672];
    int tid = threadIdx.x;
    for (int i = tid; i < 196; i += blockDim.x) {
        sw[i] = Wq[i]; sw[224 + i] = Wk[i]; sw[448 + i] = Wv[i];
    }
    if (tid < 28) { sw[196 + tid] = bq[tid]; sw[420 + tid] = bk[tid]; sw[644 + tid] = bv[tid]; }
    __syncthreads();

    int r = blockIdx.x * blockDim.x + tid;        // 0..16383
    int b = r >> 10, s = r & 1023;

    float xv[7];
#pragma unroll
    for (int i = 0; i < 7; i++) xv[i] = x[r * 7 + i];

#pragma unroll
    for (int h = 0; h < 7; h++) {
        float qa[4], ka[4], va[4];
#pragma unroll
        for (int d = 0; d < 4; d++) {
            int j = h * 4 + d;
            float aq = sw[196 + j], ak = sw[420 + j], av = sw[644 + j];
#pragma unroll
            for (int i = 0; i < 7; i++) {
                float xi = xv[i];
                aq += xi * sw[i * 28 + j];
                ak += xi * sw[224 + i * 28 + j];
                av += xi * sw[448 + i * 28 + j];
            }
            qa[d] = aq; ka[d] = ak; va[d] = av;
        }
        int o = (b * 7 + h) * 1024 + s;
        reinterpret_cast<float4*>(g_Q)[o] = make_float4(qa[0], qa[1], qa[2], qa[3]);
        reinterpret_cast<float4*>(g_K)[o] = make_float4(ka[0], ka[1], ka[2], ka[3]);
        reinterpret_cast<float4*>(g_V)[o] = make_float4(va[0], va[1], va[2], va[3]);
    }
}

// ---------------------------------------------------------------------------
// K2: first attention. 2 q rows per thread packed f32x2; K/V duplicated (k,k)
// in smem so each broadcast LDS serves both rows. Max-free softmax, ex2.approx.
// 128 thr, grid (4,7,16)=448 -> 3.03 waves; smem 64KB -> 3 CTA/SM = 12 warps.
// ---------------------------------------------------------------------------
__global__ void __launch_bounds__(128) k_attn1() {
    extern __shared__ ulonglong2 s1[];           // [0,2048): Kdup, [2048,4096): Vdup
    ulonglong2* Ks = s1;
    ulonglong2* Vs = s1 + 2048;
    int b = blockIdx.z, h = blockIdx.y, chunk = blockIdx.x;   // chunk in [0,4)
    int bh = b * 7 + h;
    const float4* Kg = reinterpret_cast<const float4*>(g_K) + bh * 1024;
    const float4* Vg = reinterpret_cast<const float4*>(g_V) + bh * 1024;
    for (int t = threadIdx.x; t < 1024; t += 128) {
        float4 kk = Kg[t];
        Ks[2*t]   = make_ulonglong2(pk2(kk.x, kk.x), pk2(kk.y, kk.y));
        Ks[2*t+1] = make_ulonglong2(pk2(kk.z, kk.z), pk2(kk.w, kk.w));
        float4 vv = Vg[t];
        Vs[2*t]   = make_ulonglong2(pk2(vv.x, vv.x), pk2(vv.y, vv.y));
        Vs[2*t+1] = make_ulonglong2(pk2(vv.z, vv.z), pk2(vv.w, vv.w));
    }
    __syncthreads();

    int qA = chunk * 256 + threadIdx.x;          // rows qA, qA+128
    float4 qa = reinterpret_cast<const float4*>(g_Q)[bh * 1024 + qA];
    float4 qb = reinterpret_cast<const float4*>(g_Q)[bh * 1024 + qA + 128];
    const float c = 0.5f * 1.4426950408889634f;  // 1/sqrt(4) * log2(e)
    u64 qp0 = pk2(qa.x * c, qb.x * c);
    u64 qp1 = pk2(qa.y * c, qb.y * c);
    u64 qp2 = pk2(qa.z * c, qb.z * c);
    u64 qp3 = pk2(qa.w * c, qb.w * c);

    u64 acc0 = 0ull, acc1 = 0ull, acc2 = 0ull, acc3 = 0ull, l2 = 0ull;
#pragma unroll 4
    for (int k = 0; k < 1024; k++) {
        ulonglong2 k01 = Ks[2*k];
        ulonglong2 k23 = Ks[2*k+1];
        u64 s2 = f2mul(qp0, k01.x);
        s2 = f2fma(qp1, k01.y, s2);
        s2 = f2fma(qp2, k23.x, s2);
        s2 = f2fma(qp3, k23.y, s2);
        float sa, sb; up2(s2, sa, sb);
        u64 p2 = pk2(ex2(sa), ex2(sb));
        ulonglong2 v01 = Vs[2*k];
        ulonglong2 v23 = Vs[2*k+1];
        acc0 = f2fma(p2, v01.x, acc0);
        acc1 = f2fma(p2, v01.y, acc1);
        acc2 = f2fma(p2, v23.x, acc2);
        acc3 = f2fma(p2, v23.y, acc3);
        l2 = f2add(l2, p2);
    }
    float lA, lB; up2(l2, lA, lB);
    float iA = 1.f / lA, iB = 1.f / lB;
    float x0, y0, x1, y1, x2, y2, x3, y3;
    up2(acc0, x0, y0); up2(acc1, x1, y1); up2(acc2, x2, y2); up2(acc3, x3, y3);
    *reinterpret_cast<float4*>(g_AO + ((b * 1024 + qA) * 28 + h * 4)) =
        make_float4(x0 * iA, x1 * iA, x2 * iA, x3 * iA);
    *reinterpret_cast<float4*>(g_AO + ((b * 1024 + qA + 128) * 28 + h * 4)) =
        make_float4(y0 * iB, y1 * iB, y2 * iB, y3 * iB);
}

// ---------------------------------------------------------------------------
// K3: LayerNorm(28) + FFN(28->7) + ReLU + residual -> out7 (d_out head),
// then Q2/K2 projections (7->28) into scratch. 1 thread per row.
// ---------------------------------------------------------------------------
__global__ void k_lnffn(const float* __restrict__ x,
                        const float* __restrict__ lnw, const float* __restrict__ lnb,
                        const float* __restrict__ W1,  const float* __restrict__ b1,
                        const float* __restrict__ Wq2, const float* __restrict__ bq2,
                        const float* __restrict__ Wk2, const float* __restrict__ bk2,
                        float* __restrict__ out7) {
    __shared__ float s_lnw[28], s_lnb[28], s_W1[196], s_b1[7];
    __shared__ float s_Wq2[196], s_bq2[28], s_Wk2[196], s_bk2[28];
    int tid = threadIdx.x;
    for (int i = tid; i < 196; i += blockDim.x) { s_W1[i] = W1[i]; s_Wq2[i] = Wq2[i]; s_Wk2[i] = Wk2[i]; }
    if (tid < 28) { s_lnw[tid] = lnw[tid]; s_lnb[tid] = lnb[tid]; s_bq2[tid] = bq2[tid]; s_bk2[tid] = bk2[tid]; }
    if (tid < 7)  { s_b1[tid] = b1[tid]; }
    __syncthreads();

    int r = blockIdx.x * blockDim.x + tid;
    float a[28];
    const float4* ap = reinterpret_cast<const float4*>(g_AO + r * 28);
#pragma unroll
    for (int i = 0; i < 7; i++) {
        float4 t = ap[i];
        a[4*i] = t.x; a[4*i+1] = t.y; a[4*i+2] = t.z; a[4*i+3] = t.w;
    }
    float mu = 0.f;
#pragma unroll
    for (int j = 0; j < 28; j++) mu += a[j];
    mu *= (1.f / 28.f);
    float var = 0.f;
#pragma unroll
    for (int j = 0; j < 28; j++) { float d = a[j] - mu; var += d * d; }
    var *= (1.f / 28.f);
    float rs = rsqrtf(var + 1e-5f);

    float y[28];
#pragma unroll
    for (int j = 0; j < 28; j++) y[j] = (a[j] - mu) * rs * s_lnw[j] + s_lnb[j];

    float z[7];
#pragma unroll
    for (int i = 0; i < 7; i++) {
        float t = s_b1[i];
#pragma unroll
        for (int j = 0; j < 28; j++) t += y[j] * s_W1[j * 7 + i];
        t = fmaxf(t, 0.f) + x[r * 7 + i];
        z[i] = t;
        out7[r * 7 + i] = t;
    }
#pragma unroll
    for (int j = 0; j < 28; j++) {
        float tq = s_bq2[j], tk = s_bk2[j];
#pragma unroll
        for (int i = 0; i < 7; i++) {
            tq += z[i] * s_Wq2[i * 28 + j];
            tk += z[i] * s_Wk2[i * 28 + j];
        }
        g_Q2[r * 28 + j] = tq;
        g_K2[r * 28 + j] = tk;
    }
}

// ---------------------------------------------------------------------------
// K4: second attention weights — K2 in registers, Q2 broadcast from smem.
// Block = 512 thr (16 warps). Thread owns ADJACENT k rows {2m, 2m+1}
// (m = warp*32+lane) so (pA,pB) packs into one STG.64 (contiguous 256B/warp).
// No per-q shfl: row sums are computed in the normalize pass, where each warp
// owns 2 whole q-rows (8 LDG.128/lane, sum, 5 shfl, scale, 8 STG.128).
// ---------------------------------------------------------------------------
__global__ void __launch_bounds__(512, 1) k_attn2(float* __restrict__ out) {
    __shared__ float sQ[32 * 28];          // q tile (scaled)

    int b = blockIdx.y, tile = blockIdx.x;             // 32 tiles of 32 q rows
    int warp = threadIdx.x >> 5, lane = threadIdx.x & 31;
    const float SC2 = 1.4426950408889634f / 2.6457513110645906f; // log2(e)/sqrt(7)

    // Load + scale Q2 tile into smem
    for (int t = threadIdx.x; t < 32 * 28; t += 512)
        sQ[t] = g_Q2[(b * 1024 + tile * 32) * 28 + t] * SC2;

    // This thread's two adjacent K2 rows -> registers (once per block)
    int m = warp * 32 + lane;                           // 0..511
    ulonglong2 kA[7], kB[7];
    {
        const ulonglong2* a = reinterpret_cast<const ulonglong2*>(g_K2 + (b * 1024 + 2 * m) * 28);
        const ulonglong2* c = reinterpret_cast<const ulonglong2*>(g_K2 + (b * 1024 + 2 * m + 1) * 28);
#pragma unroll
        for (int j = 0; j < 7; j++) { kA[j] = a[j]; kB[j] = c[j]; }
    }
    __syncthreads();

    float* obase = out + (b * 1024 + tile * 32) * 1024;

#pragma unroll 2
    for (int q = 0; q < 32; q++) {
        const ulonglong2* qp = reinterpret_cast<const ulonglong2*>(sQ + q * 28);
        ulonglong2 qv[7];
#pragma unroll
        for (int j = 0; j < 7; j++) qv[j] = qp[j];      // broadcast LDS (N=1)

        u64 accA = f2mul(qv[0].x, kA[0].x);
        u64 accB = f2mul(qv[0].x, kB[0].x);
        accA = f2fma(qv[0].y, kA[0].y, accA);  accB = f2fma(qv[0].y, kB[0].y, accB);
        accA = f2fma(qv[1].x, kA[1].x, accA);  accB = f2fma(qv[1].x, kB[1].x, accB);
        accA = f2fma(qv[1].y, kA[1].y, accA);  accB = f2fma(qv[1].y, kB[1].y, accB);
        accA = f2fma(qv[2].x, kA[2].x, accA);  accB = f2fma(qv[2].x, kB[2].x, accB);
        accA = f2fma(qv[2].y, kA[2].y, accA);  accB = f2fma(qv[2].y, kB[2].y, accB);
        accA = f2fma(qv[3].x, kA[3].x, accA);  accB = f2fma(qv[3].x, kB[3].x, accB);
        accA = f2fma(qv[3].y, kA[3].y, accA);  accB = f2fma(qv[3].y, kB[3].y, accB);
        accA = f2fma(qv[4].x, kA[4].x, accA);  accB = f2fma(qv[4].x, kB[4].x, accB);
        accA = f2fma(qv[4].y, kA[4].y, accA);  accB = f2fma(qv[4].y, kB[4].y, accB);
        accA = f2fma(qv[5].x, kA[5].x, accA);  accB = f2fma(qv[5].x, kB[5].x, accB);
        accA = f2fma(qv[5].y, kA[5].y, accA);  accB = f2fma(qv[5].y, kB[5].y, accB);
        accA = f2fma(qv[6].x, kA[6].x, accA);  accB = f2fma(qv[6].x, kB[6].x, accB);
        accA = f2fma(qv[6].y, kA[6].y, accA);  accB = f2fma(qv[6].y, kB[6].y, accB);

        float aLo, aHi, bLo, bHi;
        up2(accA, aLo, aHi); up2(accB, bLo, bHi);
        float pA = ex2(aLo + aHi);
        float pB = ex2(bLo + bHi);

        // one STG.64: (pA, pB) at columns (2m, 2m+1)
        *reinterpret_cast<u64*>(&obase[q * 1024 + 2 * m]) = pk2(pA, pB);
    }
    __syncthreads();   // make all warps' global p-writes visible block-wide

    // Normalize pass: each warp owns q-rows {warp, warp+16}.
#pragma unroll
    for (int rr = 0; rr < 2; rr++) {
        int q = warp + rr * 16;
        float4* row = reinterpret_cast<float4*>(obase + q * 1024);
        float4 v[8];
#pragma unroll
        for (int i = 0; i < 8; i++) v[i] = row[i * 32 + lane];
        float s = 0.f;
#pragma unroll
        for (int i = 0; i < 8; i++) s += (v[i].x + v[i].y) + (v[i].z + v[i].w);
#pragma unroll
        for (int o = 16; o > 0; o >>= 1)
            s += __shfl_xor_sync(0xffffffffu, s, o);
        float iv = 1.f / s;
#pragma unroll
        for (int i = 0; i < 8; i++) {
            v[i].x *= iv; v[i].y *= iv; v[i].z *= iv; v[i].w *= iv;
            row[i * 32 + lane] = v[i];
        }
    }
}

// ---------------------------------------------------------------------------
extern "C" void kernel_launch(void* const* d_in, const int* in_sizes, int n_in,
                              void* d_out, int out_size) {
    const float* x    = (const float*)d_in[0];
    const float* Wq   = (const float*)d_in[1];
    const float* bq   = (const float*)d_in[2];
    const float* Wk   = (const float*)d_in[3];
    const float* bk   = (const float*)d_in[4];
    const float* Wv   = (const float*)d_in[5];
    const float* bv   = (const float*)d_in[6];
    const float* lnw  = (const float*)d_in[7];
    const float* lnb  = (const float*)d_in[8];
    const float* W1   = (const float*)d_in[9];
    const float* b1   = (const float*)d_in[10];
    const float* Wq2  = (const float*)d_in[11];
    const float* bq2  = (const float*)d_in[12];
    const float* Wk2  = (const float*)d_in[13];
    const float* bk2  = (const float*)d_in[14];
    float* out = (float*)d_out;

    cudaFuncSetAttribute(k_attn1, cudaFuncAttributeMaxDynamicSharedMemorySize, 65536);

    k_qkv<<<128, 128>>>(x, Wq, bq, Wk, bk, Wv, bv);
    k_attn1<<<dim3(4, 7, 16), 128, 65536>>>();
    k_lnffn<<<128, 128>>>(x, lnw, lnb, W1, b1, Wq2, bq2, Wk2, bk2, out);
    k_attn2<<<dim3(32, 16), 512>>>(out + BB * SS * NIN);
}